// round 3
// baseline (speedup 1.0000x reference)
#include <cuda_runtime.h>

#define N_NODES 50000
#define N_EDGES 800000
#define HEADS 8
#define HID 32
#define F_IN 256
#define F_H 256      /* HEADS*HID */
#define F_OUT 16
#define NEG 0.2f

// ---------------- static device scratch (no runtime allocation) ----------------
__device__ float g_h1 [N_NODES * F_H];    // layer1 linear output  [N,256]
__device__ float g_h1b[N_NODES * F_H];    // layer1 aggregated+relu output [N,256]
__device__ float g_als1[N_NODES * HEADS];
__device__ float g_ald1[N_NODES * HEADS];
__device__ float g_h2 [N_NODES * F_OUT];  // layer2 linear output [N,16]
__device__ float g_als2[N_NODES];
__device__ float g_ald2[N_NODES];
__device__ int   g_cnt [N_NODES];
__device__ int   g_fill[N_NODES];
__device__ int   g_rowptr[N_NODES + 1];
__device__ int   g_col [N_EDGES];         // src node per CSR slot (sorted by dst)

__device__ __forceinline__ float lrelu(float x) { return x > 0.f ? x : NEG * x; }
__device__ __forceinline__ int   clampn(int v) {
    return v < 0 ? 0 : (v >= N_NODES ? N_NODES - 1 : v);
}

// ---------------- CSR build ----------------
__global__ void k_zero() {
    int i = blockIdx.x * blockDim.x + threadIdx.x;
    if (i < N_NODES) { g_cnt[i] = 0; g_fill[i] = 0; }
}

__global__ void k_hist(const int* __restrict__ ei) {
    int e = blockIdx.x * blockDim.x + threadIdx.x;
    if (e < N_EDGES) atomicAdd(&g_cnt[clampn(ei[N_EDGES + e])], 1);
}

__global__ void k_scan() {
    __shared__ int sh[1024];
    __shared__ int s_carry;
    int t = threadIdx.x;
    if (t == 0) s_carry = 0;
    __syncthreads();
    for (int base = 0; base < N_NODES; base += 1024) {
        int i = base + t;
        int v = (i < N_NODES) ? g_cnt[i] : 0;
        sh[t] = v;
        __syncthreads();
        for (int off = 1; off < 1024; off <<= 1) {
            int add = (t >= off) ? sh[t - off] : 0;
            __syncthreads();
            sh[t] += add;
            __syncthreads();
        }
        int carry = s_carry;
        if (i < N_NODES) g_rowptr[i] = carry + sh[t] - v;   // exclusive
        int total = sh[1023];
        __syncthreads();
        if (t == 0) s_carry = carry + total;
        __syncthreads();
    }
    if (t == 0) g_rowptr[N_NODES] = s_carry;
}

__global__ void k_scatter(const int* __restrict__ ei) {
    int e = blockIdx.x * blockDim.x + threadIdx.x;
    if (e < N_EDGES) {
        int dst = clampn(ei[N_EDGES + e]);
        int pos = g_rowptr[dst] + atomicAdd(&g_fill[dst], 1);
        g_col[pos] = clampn(ei[e]);
    }
}

// ---------------- GEMM1: g_h1 = X[50000,256] @ W1[256,256] ----------------
__global__ __launch_bounds__(256) void k_gemm1(const float* __restrict__ X,
                                               const float* __restrict__ W) {
    __shared__ float As[16][65];   // padded: avoid bank conflicts on k-major store
    __shared__ float Bs[16][64];
    int tid = threadIdx.x;
    int tx = tid & 15, ty = tid >> 4;
    int m0 = blockIdx.x * 64, n0 = blockIdx.y * 64;
    float acc[4][4];
#pragma unroll
    for (int i = 0; i < 4; i++)
#pragma unroll
        for (int j = 0; j < 4; j++) acc[i][j] = 0.f;

    for (int k0 = 0; k0 < F_IN; k0 += 16) {
#pragma unroll
        for (int r = 0; r < 4; r++) {               // A tile 64x16
            int idx = tid + r * 256;
            int m = idx >> 4, k = idx & 15;
            int gm = m0 + m;
            As[k][m] = (gm < N_NODES) ? X[gm * F_IN + k0 + k] : 0.f;
        }
#pragma unroll
        for (int r = 0; r < 4; r++) {               // B tile 16x64
            int idx = tid + r * 256;
            int k = idx >> 6, nn = idx & 63;
            Bs[k][nn] = W[(k0 + k) * F_H + n0 + nn];
        }
        __syncthreads();
#pragma unroll
        for (int kk = 0; kk < 16; kk++) {
            float a[4], b[4];
#pragma unroll
            for (int i = 0; i < 4; i++) a[i] = As[kk][ty * 4 + i];
#pragma unroll
            for (int j = 0; j < 4; j++) b[j] = Bs[kk][tx * 4 + j];
#pragma unroll
            for (int i = 0; i < 4; i++)
#pragma unroll
                for (int j = 0; j < 4; j++) acc[i][j] += a[i] * b[j];
        }
        __syncthreads();
    }
#pragma unroll
    for (int i = 0; i < 4; i++) {
        int gm = m0 + ty * 4 + i;
        if (gm < N_NODES) {
#pragma unroll
            for (int j = 0; j < 4; j++)
                g_h1[gm * F_H + n0 + tx * 4 + j] = acc[i][j];
        }
    }
}

// ---------------- attention coefficient dots, layer 1 (warp per node) ----------
__global__ void k_dots1(const float* __restrict__ as1, const float* __restrict__ ad1) {
    int warp = threadIdx.x >> 5, lane = threadIdx.x & 31;
    int n = blockIdx.x * 8 + warp;
    if (n >= N_NODES) return;
    const float* hp = g_h1 + n * F_H;
#pragma unroll
    for (int h = 0; h < HEADS; h++) {
        float v = hp[h * 32 + lane];
        float ps = v * as1[h * 32 + lane];
        float pd = v * ad1[h * 32 + lane];
#pragma unroll
        for (int off = 16; off; off >>= 1) {
            ps += __shfl_xor_sync(0xffffffffu, ps, off);
            pd += __shfl_xor_sync(0xffffffffu, pd, off);
        }
        if (lane == 0) { g_als1[n * HEADS + h] = ps; g_ald1[n * HEADS + h] = pd; }
    }
}

// ---------------- layer 1 softmax-aggregate (warp per dst node) ----------------
// virtual self-loop appended as edge index j == deg (src = n)
__global__ void k_agg1(const float* __restrict__ b1) {
    int warp = threadIdx.x >> 5, lane = threadIdx.x & 31;
    int n = blockIdx.x * 8 + warp;
    if (n >= N_NODES) return;
    int row = g_rowptr[n];
    int deg = g_rowptr[n + 1] - row;
    int cnt = deg + 1;
    int h = lane & 7;                       // this lane's head for e/alpha
    float ald = g_ald1[n * HEADS + h];

    // pass 1: per-head max (lanes: 4 edges x 8 heads per iteration)
    float mh = -1e30f;
    for (int j = lane >> 3; j < cnt; j += 4) {
        int src = (j < deg) ? g_col[row + j] : n;
        mh = fmaxf(mh, lrelu(g_als1[src * HEADS + h] + ald));
    }
    mh = fmaxf(mh, __shfl_xor_sync(0xffffffffu, mh, 8));
    mh = fmaxf(mh, __shfl_xor_sync(0xffffffffu, mh, 16));

    // pass 2: per-head sum of exp
    float sh = 0.f;
    for (int j = lane >> 3; j < cnt; j += 4) {
        int src = (j < deg) ? g_col[row + j] : n;
        sh += __expf(lrelu(g_als1[src * HEADS + h] + ald) - mh);
    }
    sh += __shfl_xor_sync(0xffffffffu, sh, 8);
    sh += __shfl_xor_sync(0xffffffffu, sh, 16);
    float rinv = __fdividef(1.f, sh);

    // pass 3: weighted feature gather. acc[k] holds feature k*32+lane (head k).
    float acc[8];
#pragma unroll
    for (int k = 0; k < 8; k++) acc[k] = 0.f;
    for (int j = 0; j < cnt; j++) {
        int src = (j < deg) ? g_col[row + j] : n;
        float w = __expf(lrelu(g_als1[src * HEADS + h] + ald) - mh) * rinv; // alpha for head h=lane&7
        const float* hp = g_h1 + src * F_H;
#pragma unroll
        for (int k = 0; k < 8; k++) {
            float wk = __shfl_sync(0xffffffffu, w, k);   // lane k holds head k's alpha
            acc[k] += wk * hp[k * 32 + lane];
        }
    }
#pragma unroll
    for (int k = 0; k < 8; k++) {
        float v = acc[k] + b1[k * 32 + lane];
        g_h1b[n * F_H + k * 32 + lane] = fmaxf(v, 0.f);   // relu
    }
}

// ---------------- layer 2 GEMM (50000x16x256) + attention dots ----------------
__global__ void k_gemm2(const float* __restrict__ W2,
                        const float* __restrict__ as2, const float* __restrict__ ad2) {
    __shared__ float sW[F_OUT * 256];    // transposed: sW[j*256 + k]
    int tid = threadIdx.x;
    for (int idx = tid; idx < F_OUT * 256; idx += blockDim.x) {
        int j = idx >> 8, k = idx & 255;
        sW[idx] = W2[k * F_OUT + j];
    }
    __syncthreads();
    int warp = tid >> 5, lane = tid & 31;
    int n = blockIdx.x * 8 + warp;
    if (n >= N_NODES) return;
    const float* hp = g_h1b + n * 256;
    float acc[F_OUT];
#pragma unroll
    for (int j = 0; j < F_OUT; j++) acc[j] = 0.f;
    for (int k = lane; k < 256; k += 32) {
        float xv = hp[k];
#pragma unroll
        for (int j = 0; j < F_OUT; j++) acc[j] += xv * sW[j * 256 + k];
    }
#pragma unroll
    for (int j = 0; j < F_OUT; j++)
#pragma unroll
        for (int off = 16; off; off >>= 1)
            acc[j] += __shfl_xor_sync(0xffffffffu, acc[j], off);
    if (lane == 0) {
        float s = 0.f, d = 0.f;
#pragma unroll
        for (int j = 0; j < F_OUT; j++) {
            g_h2[n * F_OUT + j] = acc[j];
            s += acc[j] * as2[j];
            d += acc[j] * ad2[j];
        }
        g_als2[n] = s;
        g_ald2[n] = d;
    }
}

// ---------------- layer 2 softmax-aggregate + log_softmax (warp per node) ------
__global__ void k_agg2(const float* __restrict__ b2, float* __restrict__ out) {
    int warp = threadIdx.x >> 5, lane = threadIdx.x & 31;
    int n = blockIdx.x * 8 + warp;
    if (n >= N_NODES) return;
    int row = g_rowptr[n];
    int deg = g_rowptr[n + 1] - row;
    int cnt = deg + 1;
    float ald = g_ald2[n];

    float mx = -1e30f;
    for (int j = lane; j < cnt; j += 32) {
        int src = (j < deg) ? g_col[row + j] : n;
        mx = fmaxf(mx, lrelu(g_als2[src] + ald));
    }
#pragma unroll
    for (int off = 16; off; off >>= 1) mx = fmaxf(mx, __shfl_xor_sync(0xffffffffu, mx, off));

    float s = 0.f;
    for (int j = lane; j < cnt; j += 32) {
        int src = (j < deg) ? g_col[row + j] : n;
        s += __expf(lrelu(g_als2[src] + ald) - mx);
    }
#pragma unroll
    for (int off = 16; off; off >>= 1) s += __shfl_xor_sync(0xffffffffu, s, off);
    float rinv = __fdividef(1.f, s);

    // aggregation: 2 edges per iteration, 16 channels each
    int c = lane & 15, half = lane >> 4;
    float acc = 0.f;
    for (int j = half; j < cnt; j += 2) {
        int src = (j < deg) ? g_col[row + j] : n;
        float w = __expf(lrelu(g_als2[src] + ald) - mx) * rinv;
        acc += w * g_h2[src * F_OUT + c];
    }
    acc += __shfl_xor_sync(0xffffffffu, acc, 16);

    float v = acc + b2[c];
    // log_softmax across the 16-lane group
    float m2 = v;
#pragma unroll
    for (int off = 1; off < 16; off <<= 1) m2 = fmaxf(m2, __shfl_xor_sync(0xffffffffu, m2, off));
    float s2 = __expf(v - m2);
#pragma unroll
    for (int off = 1; off < 16; off <<= 1) s2 += __shfl_xor_sync(0xffffffffu, s2, off);
    float o = v - m2 - __logf(s2);
    if (lane < 16) out[n * F_OUT + c] = o;
}

// ---------------- launch ----------------
extern "C" void kernel_launch(void* const* d_in, const int* in_sizes, int n_in,
                              void* d_out, int out_size) {
    const float* x   = (const float*)d_in[0];
    const int*   ei  = (const int*)d_in[1];    // int32: JAX demotes int64 w/o x64
    const float* W1  = (const float*)d_in[2];
    const float* as1 = (const float*)d_in[3];
    const float* ad1 = (const float*)d_in[4];
    const float* b1  = (const float*)d_in[5];
    const float* W2  = (const float*)d_in[6];
    const float* as2 = (const float*)d_in[7];
    const float* ad2 = (const float*)d_in[8];
    const float* b2  = (const float*)d_in[9];
    float* out = (float*)d_out;

    k_zero<<<(N_NODES + 255) / 256, 256>>>();
    k_hist<<<(N_EDGES + 255) / 256, 256>>>(ei);
    k_scan<<<1, 1024>>>();
    k_scatter<<<(N_EDGES + 255) / 256, 256>>>(ei);

    dim3 g1((N_NODES + 63) / 64, F_H / 64);
    k_gemm1<<<g1, 256>>>(x, W1);
    k_dots1<<<(N_NODES + 7) / 8, 256>>>(as1, ad1);
    k_agg1<<<(N_NODES + 7) / 8, 256>>>(b1);
    k_gemm2<<<(N_NODES + 7) / 8, 256>>>(W2, as2, ad2);
    k_agg2<<<(N_NODES + 7) / 8, 256>>>(b2, out);
}

// round 4
// speedup vs baseline: 1.2566x; 1.2566x over previous
#include <cuda_runtime.h>

#define N_NODES 50000
#define N_EDGES 800000
#define HEADS 8
#define HID 32
#define F_IN 256
#define F_H 256      /* HEADS*HID */
#define F_OUT 16
#define NEG 0.2f
#define SCAN_BLOCKS 196   /* ceil(50000/256) */

// ---------------- static device scratch (no runtime allocation) ----------------
__device__ float g_h1 [N_NODES * F_H];    // layer1 linear output  [N,256]
__device__ float g_h1b[N_NODES * F_H];    // layer1 aggregated+relu output [N,256]
__device__ float g_als1[N_NODES * HEADS];
__device__ float g_ald1[N_NODES * HEADS];
__device__ float g_h2 [N_NODES * F_OUT];  // layer2 linear output [N,16]
__device__ float g_als2[N_NODES];
__device__ float g_ald2[N_NODES];
__device__ int   g_cnt [N_NODES];
__device__ int   g_fill[N_NODES];
__device__ int   g_rowptr[N_NODES + 1];
__device__ int   g_col [N_EDGES];         // src node per CSR slot (sorted by dst)
__device__ int   g_bsum[256];
__device__ int   g_boff[256];

__device__ __forceinline__ float lrelu(float x) { return x > 0.f ? x : NEG * x; }
__device__ __forceinline__ int   clampn(int v) {
    return v < 0 ? 0 : (v >= N_NODES ? N_NODES - 1 : v);
}

// ---------------- CSR build ----------------
__global__ void k_zero() {
    int i = blockIdx.x * blockDim.x + threadIdx.x;
    if (i < N_NODES) { g_cnt[i] = 0; g_fill[i] = 0; }
}

__global__ void k_hist(const int* __restrict__ ei) {
    int e = blockIdx.x * blockDim.x + threadIdx.x;
    if (e < N_EDGES) atomicAdd(&g_cnt[clampn(ei[N_EDGES + e])], 1);
}

// block sums of g_cnt (256 per block)
__global__ void k_blocksum() {
    int t = threadIdx.x, i = blockIdx.x * 256 + t;
    int v = (i < N_NODES) ? g_cnt[i] : 0;
#pragma unroll
    for (int off = 16; off; off >>= 1) v += __shfl_xor_sync(0xffffffffu, v, off);
    __shared__ int ws[8];
    if ((t & 31) == 0) ws[t >> 5] = v;
    __syncthreads();
    if (t == 0) {
        int s = 0;
#pragma unroll
        for (int w = 0; w < 8; w++) s += ws[w];
        g_bsum[blockIdx.x] = s;
    }
}

// single-block scan of the 196 block sums -> exclusive offsets + total
__global__ void k_scan_bsum() {
    __shared__ int sh[256];
    int t = threadIdx.x;
    int v = (t < SCAN_BLOCKS) ? g_bsum[t] : 0;
    sh[t] = v;
    __syncthreads();
    for (int off = 1; off < 256; off <<= 1) {
        int a = (t >= off) ? sh[t - off] : 0;
        __syncthreads();
        sh[t] += a;
        __syncthreads();
    }
    g_boff[t] = sh[t] - v;              // exclusive
    if (t == 255) g_rowptr[N_NODES] = sh[255];
}

// per-block exclusive scan + block offset -> g_rowptr
__global__ void k_scan_final() {
    int t = threadIdx.x, i = blockIdx.x * 256 + t;
    int lane = t & 31, wid = t >> 5;
    int v = (i < N_NODES) ? g_cnt[i] : 0;
    int x = v;
#pragma unroll
    for (int off = 1; off < 32; off <<= 1) {
        int y = __shfl_up_sync(0xffffffffu, x, off);
        if (lane >= off) x += y;
    }
    __shared__ int ws[8];
    if (lane == 31) ws[wid] = x;
    __syncthreads();
    if (wid == 0 && lane < 8) {
        int y = ws[lane];
#pragma unroll
        for (int off = 1; off < 8; off <<= 1) {
            int z = __shfl_up_sync(0xffu, y, off, 8);
            if (lane >= off) y += z;
        }
        ws[lane] = y;
    }
    __syncthreads();
    int wexcl = (wid > 0) ? ws[wid - 1] : 0;
    if (i < N_NODES) g_rowptr[i] = (x - v) + wexcl + g_boff[blockIdx.x];
}

__global__ void k_scatter(const int* __restrict__ ei) {
    int e = blockIdx.x * blockDim.x + threadIdx.x;
    if (e < N_EDGES) {
        int dst = clampn(ei[N_EDGES + e]);
        int pos = g_rowptr[dst] + atomicAdd(&g_fill[dst], 1);
        g_col[pos] = clampn(ei[e]);
    }
}

// ---------------- GEMM1: g_h1 = X[50000,256] @ W1[256,256] ----------------
// 128x128 block tile, 8x8 microtile, BK=8, double-buffered smem, float4 I/O.
__global__ __launch_bounds__(256) void k_gemm1(const float* __restrict__ X,
                                               const float* __restrict__ W) {
    __shared__ float As[2][8][132];   // k-major (transposed), padded
    __shared__ float Bs[2][8][128];
    int tid = threadIdx.x;
    int m0 = blockIdx.x * 128, n0 = blockIdx.y * 128;
    int tx = tid & 15, ty = tid >> 4;

    int arow = tid >> 1, akq = tid & 1;       // A: 128 rows x 2 float4 along k
    int brow = tid >> 5, bcol4 = (tid & 31) * 4;  // B: 8 rows x 32 float4 along n

    float4 aPre, bPre;
    {
        int gm = m0 + arow;
        aPre = (gm < N_NODES) ? *(const float4*)(X + (size_t)gm * F_IN + akq * 4)
                              : make_float4(0.f, 0.f, 0.f, 0.f);
        bPre = *(const float4*)(W + (size_t)brow * F_H + n0 + bcol4);
    }
    As[0][akq * 4 + 0][arow] = aPre.x;
    As[0][akq * 4 + 1][arow] = aPre.y;
    As[0][akq * 4 + 2][arow] = aPre.z;
    As[0][akq * 4 + 3][arow] = aPre.w;
    *(float4*)&Bs[0][brow][bcol4] = bPre;
    __syncthreads();

    float acc[8][8];
#pragma unroll
    for (int i = 0; i < 8; i++)
#pragma unroll
        for (int j = 0; j < 8; j++) acc[i][j] = 0.f;

    int buf = 0;
    for (int p = 0; p < F_IN / 8; p++) {
        if (p < F_IN / 8 - 1) {
            int k0 = (p + 1) * 8;
            int gm = m0 + arow;
            aPre = (gm < N_NODES)
                 ? *(const float4*)(X + (size_t)gm * F_IN + k0 + akq * 4)
                 : make_float4(0.f, 0.f, 0.f, 0.f);
            bPre = *(const float4*)(W + (size_t)(k0 + brow) * F_H + n0 + bcol4);
        }
#pragma unroll
        for (int k = 0; k < 8; k++) {
            float a[8], b[8];
            *(float4*)&a[0] = *(float4*)&As[buf][k][ty * 8];
            *(float4*)&a[4] = *(float4*)&As[buf][k][ty * 8 + 4];
            *(float4*)&b[0] = *(float4*)&Bs[buf][k][tx * 8];
            *(float4*)&b[4] = *(float4*)&Bs[buf][k][tx * 8 + 4];
#pragma unroll
            for (int i = 0; i < 8; i++)
#pragma unroll
                for (int j = 0; j < 8; j++) acc[i][j] += a[i] * b[j];
        }
        if (p < F_IN / 8 - 1) {
            buf ^= 1;
            As[buf][akq * 4 + 0][arow] = aPre.x;
            As[buf][akq * 4 + 1][arow] = aPre.y;
            As[buf][akq * 4 + 2][arow] = aPre.z;
            As[buf][akq * 4 + 3][arow] = aPre.w;
            *(float4*)&Bs[buf][brow][bcol4] = bPre;
            __syncthreads();
        }
    }
#pragma unroll
    for (int i = 0; i < 8; i++) {
        int gm = m0 + ty * 8 + i;
        if (gm < N_NODES) {
            float4 v0 = make_float4(acc[i][0], acc[i][1], acc[i][2], acc[i][3]);
            float4 v1 = make_float4(acc[i][4], acc[i][5], acc[i][6], acc[i][7]);
            *(float4*)(g_h1 + (size_t)gm * F_H + n0 + tx * 8)     = v0;
            *(float4*)(g_h1 + (size_t)gm * F_H + n0 + tx * 8 + 4) = v1;
        }
    }
}

// ---------------- attention coefficient dots, layer 1 (warp per node) ----------
__global__ void k_dots1(const float* __restrict__ as1, const float* __restrict__ ad1) {
    int warp = threadIdx.x >> 5, lane = threadIdx.x & 31;
    int n = blockIdx.x * 8 + warp;
    if (n >= N_NODES) return;
    const float* hp = g_h1 + (size_t)n * F_H;
#pragma unroll
    for (int h = 0; h < HEADS; h++) {
        float v = hp[h * 32 + lane];
        float ps = v * as1[h * 32 + lane];
        float pd = v * ad1[h * 32 + lane];
#pragma unroll
        for (int off = 16; off; off >>= 1) {
            ps += __shfl_xor_sync(0xffffffffu, ps, off);
            pd += __shfl_xor_sync(0xffffffffu, pd, off);
        }
        if (lane == 0) { g_als1[n * HEADS + h] = ps; g_ald1[n * HEADS + h] = pd; }
    }
}

// ---------------- layer 1 softmax-aggregate (warp per dst node) ----------------
// virtual self-loop appended as edge index j == deg (src = n)
__global__ void k_agg1(const float* __restrict__ b1) {
    int warp = threadIdx.x >> 5, lane = threadIdx.x & 31;
    int n = blockIdx.x * 8 + warp;
    if (n >= N_NODES) return;
    int row = g_rowptr[n];
    int deg = g_rowptr[n + 1] - row;
    int cnt = deg + 1;
    int h = lane & 7;                       // this lane's head for softmax stats
    float ald = g_ald1[n * HEADS + h];

    // pass 1: per-head max (4 edges x 8 heads per iteration)
    float mh = -1e30f;
    for (int j = lane >> 3; j < cnt; j += 4) {
        int src = (j < deg) ? g_col[row + j] : n;
        mh = fmaxf(mh, lrelu(g_als1[src * HEADS + h] + ald));
    }
    mh = fmaxf(mh, __shfl_xor_sync(0xffffffffu, mh, 8));
    mh = fmaxf(mh, __shfl_xor_sync(0xffffffffu, mh, 16));

    // pass 2: per-head sum of exp
    float sh = 0.f;
    for (int j = lane >> 3; j < cnt; j += 4) {
        int src = (j < deg) ? g_col[row + j] : n;
        sh += __expf(lrelu(g_als1[src * HEADS + h] + ald) - mh);
    }
    sh += __shfl_xor_sync(0xffffffffu, sh, 8);
    sh += __shfl_xor_sync(0xffffffffu, sh, 16);
    float rinv = __fdividef(1.f, sh);

    // pass 3: each lane owns 8 contiguous channels [lane*8, lane*8+8), which
    // all belong to head hl = lane>>2. Lane hl holds head hl's stats.
    int hl = lane >> 2;
    float mh2  = __shfl_sync(0xffffffffu, mh,   hl);
    float rv2  = __shfl_sync(0xffffffffu, rinv, hl);
    float ald2 = __shfl_sync(0xffffffffu, ald,  hl);
    int c0 = lane * 8;
    float4 acc0 = make_float4(0.f, 0.f, 0.f, 0.f);
    float4 acc1 = make_float4(0.f, 0.f, 0.f, 0.f);
    for (int j = 0; j < cnt; j++) {
        int src = (j < deg) ? g_col[row + j] : n;      // broadcast load
        float w = __expf(lrelu(g_als1[src * HEADS + hl] + ald2) - mh2) * rv2;
        const float4* hp = (const float4*)(g_h1 + (size_t)src * F_H + c0);
        float4 v0 = hp[0], v1 = hp[1];
        acc0.x += w * v0.x; acc0.y += w * v0.y; acc0.z += w * v0.z; acc0.w += w * v0.w;
        acc1.x += w * v1.x; acc1.y += w * v1.y; acc1.z += w * v1.z; acc1.w += w * v1.w;
    }
    float4 bb0 = *(const float4*)(b1 + c0);
    float4 bb1 = *(const float4*)(b1 + c0 + 4);
    float4 o0, o1;
    o0.x = fmaxf(acc0.x + bb0.x, 0.f); o0.y = fmaxf(acc0.y + bb0.y, 0.f);
    o0.z = fmaxf(acc0.z + bb0.z, 0.f); o0.w = fmaxf(acc0.w + bb0.w, 0.f);
    o1.x = fmaxf(acc1.x + bb1.x, 0.f); o1.y = fmaxf(acc1.y + bb1.y, 0.f);
    o1.z = fmaxf(acc1.z + bb1.z, 0.f); o1.w = fmaxf(acc1.w + bb1.w, 0.f);
    *(float4*)(g_h1b + (size_t)n * F_H + c0)     = o0;
    *(float4*)(g_h1b + (size_t)n * F_H + c0 + 4) = o1;
}

// ---------------- layer 2 GEMM (50000x16x256) + attention dots ----------------
__global__ void k_gemm2(const float* __restrict__ W2,
                        const float* __restrict__ as2, const float* __restrict__ ad2) {
    __shared__ float sW[F_OUT * 256];    // transposed: sW[j*256 + k]
    int tid = threadIdx.x;
    for (int idx = tid; idx < F_OUT * 256; idx += blockDim.x) {
        int j = idx >> 8, k = idx & 255;
        sW[idx] = W2[k * F_OUT + j];
    }
    __syncthreads();
    int warp = tid >> 5, lane = tid & 31;
    int n = blockIdx.x * 8 + warp;
    if (n >= N_NODES) return;
    const float* hp = g_h1b + (size_t)n * 256;
    float acc[F_OUT];
#pragma unroll
    for (int j = 0; j < F_OUT; j++) acc[j] = 0.f;
    for (int k = lane; k < 256; k += 32) {
        float xv = hp[k];
#pragma unroll
        for (int j = 0; j < F_OUT; j++) acc[j] += xv * sW[j * 256 + k];
    }
#pragma unroll
    for (int j = 0; j < F_OUT; j++)
#pragma unroll
        for (int off = 16; off; off >>= 1)
            acc[j] += __shfl_xor_sync(0xffffffffu, acc[j], off);
    if (lane == 0) {
        float s = 0.f, d = 0.f;
#pragma unroll
        for (int j = 0; j < F_OUT; j++) {
            g_h2[n * F_OUT + j] = acc[j];
            s += acc[j] * as2[j];
            d += acc[j] * ad2[j];
        }
        g_als2[n] = s;
        g_ald2[n] = d;
    }
}

// ---------------- layer 2 softmax-aggregate + log_softmax (warp per node) ------
__global__ void k_agg2(const float* __restrict__ b2, float* __restrict__ out) {
    int warp = threadIdx.x >> 5, lane = threadIdx.x & 31;
    int n = blockIdx.x * 8 + warp;
    if (n >= N_NODES) return;
    int row = g_rowptr[n];
    int deg = g_rowptr[n + 1] - row;
    int cnt = deg + 1;
    float ald = g_ald2[n];

    float mx = -1e30f;
    for (int j = lane; j < cnt; j += 32) {
        int src = (j < deg) ? g_col[row + j] : n;
        mx = fmaxf(mx, lrelu(g_als2[src] + ald));
    }
#pragma unroll
    for (int off = 16; off; off >>= 1) mx = fmaxf(mx, __shfl_xor_sync(0xffffffffu, mx, off));

    float s = 0.f;
    for (int j = lane; j < cnt; j += 32) {
        int src = (j < deg) ? g_col[row + j] : n;
        s += __expf(lrelu(g_als2[src] + ald) - mx);
    }
#pragma unroll
    for (int off = 16; off; off >>= 1) s += __shfl_xor_sync(0xffffffffu, s, off);
    float rinv = __fdividef(1.f, s);

    // aggregation: 2 edges per iteration, 16 channels each
    int c = lane & 15, half = lane >> 4;
    float acc = 0.f;
    for (int j = half; j < cnt; j += 2) {
        int src = (j < deg) ? g_col[row + j] : n;
        float w = __expf(lrelu(g_als2[src] + ald) - mx) * rinv;
        acc += w * g_h2[src * F_OUT + c];
    }
    acc += __shfl_xor_sync(0xffffffffu, acc, 16);

    float v = acc + b2[c];
    // log_softmax across the 16-lane group
    float m2 = v;
#pragma unroll
    for (int off = 1; off < 16; off <<= 1) m2 = fmaxf(m2, __shfl_xor_sync(0xffffffffu, m2, off));
    float s2 = __expf(v - m2);
#pragma unroll
    for (int off = 1; off < 16; off <<= 1) s2 += __shfl_xor_sync(0xffffffffu, s2, off);
    float o = v - m2 - __logf(s2);
    if (lane < 16) out[n * F_OUT + c] = o;
}

// ---------------- launch ----------------
extern "C" void kernel_launch(void* const* d_in, const int* in_sizes, int n_in,
                              void* d_out, int out_size) {
    const float* x   = (const float*)d_in[0];
    const int*   ei  = (const int*)d_in[1];    // int32 (JAX demotes int64 w/o x64)
    const float* W1  = (const float*)d_in[2];
    const float* as1 = (const float*)d_in[3];
    const float* ad1 = (const float*)d_in[4];
    const float* b1  = (const float*)d_in[5];
    const float* W2  = (const float*)d_in[6];
    const float* as2 = (const float*)d_in[7];
    const float* ad2 = (const float*)d_in[8];
    const float* b2  = (const float*)d_in[9];
    float* out = (float*)d_out;

    k_zero<<<(N_NODES + 255) / 256, 256>>>();
    k_hist<<<(N_EDGES + 255) / 256, 256>>>(ei);
    k_blocksum<<<SCAN_BLOCKS, 256>>>();
    k_scan_bsum<<<1, 256>>>();
    k_scan_final<<<SCAN_BLOCKS, 256>>>();
    k_scatter<<<(N_EDGES + 255) / 256, 256>>>(ei);

    dim3 g1((N_NODES + 127) / 128, F_H / 128);
    k_gemm1<<<g1, 256>>>(x, W1);
    k_dots1<<<(N_NODES + 7) / 8, 256>>>(as1, ad1);
    k_agg1<<<(N_NODES + 7) / 8, 256>>>(b1);
    k_gemm2<<<(N_NODES + 7) / 8, 256>>>(W2, as2, ad2);
    k_agg2<<<(N_NODES + 7) / 8, 256>>>(b2, out);
}

// round 5
// speedup vs baseline: 1.4094x; 1.1215x over previous
#include <cuda_runtime.h>
#include <cstdint>

#define N_NODES 50000
#define N_EDGES 800000
#define HEADS 8
#define HID 32
#define F_IN 256
#define F_H 256      /* HEADS*HID */
#define F_OUT 16
#define NEG 0.2f
#define SCAN_BLOCKS 196   /* ceil(50000/256) */

// ---------------- static device scratch (no runtime allocation) ----------------
__device__ float g_h1 [N_NODES * F_H];    // layer1 linear output  [N,256]
__device__ float g_h1b[N_NODES * F_H];    // layer1 aggregated+relu output [N,256]
__device__ float g_als1[N_NODES * HEADS];
__device__ float g_ald1[N_NODES * HEADS];
__device__ float g_h2 [N_NODES * F_OUT];  // layer2 linear output [N,16]
__device__ float g_als2[N_NODES];
__device__ float g_ald2[N_NODES];
__device__ int   g_cnt [N_NODES];
__device__ int   g_fill[N_NODES];
__device__ int   g_rowptr[N_NODES + 1];
__device__ int   g_col [N_EDGES];         // src node per CSR slot (sorted by dst)
__device__ int   g_bsum[256];
__device__ int   g_boff[256];

__device__ __forceinline__ float lrelu(float x) { return x > 0.f ? x : NEG * x; }
__device__ __forceinline__ int   clampn(int v) {
    return v < 0 ? 0 : (v >= N_NODES ? N_NODES - 1 : v);
}

// ---------------- CSR build ----------------
__global__ void k_zero() {
    int i = blockIdx.x * blockDim.x + threadIdx.x;
    if (i < N_NODES) { g_cnt[i] = 0; g_fill[i] = 0; }
}

__global__ void k_hist(const int* __restrict__ ei) {
    int e = blockIdx.x * blockDim.x + threadIdx.x;
    if (e < N_EDGES) atomicAdd(&g_cnt[clampn(ei[N_EDGES + e])], 1);
}

__global__ void k_blocksum() {
    int t = threadIdx.x, i = blockIdx.x * 256 + t;
    int v = (i < N_NODES) ? g_cnt[i] : 0;
#pragma unroll
    for (int off = 16; off; off >>= 1) v += __shfl_xor_sync(0xffffffffu, v, off);
    __shared__ int ws[8];
    if ((t & 31) == 0) ws[t >> 5] = v;
    __syncthreads();
    if (t == 0) {
        int s = 0;
#pragma unroll
        for (int w = 0; w < 8; w++) s += ws[w];
        g_bsum[blockIdx.x] = s;
    }
}

__global__ void k_scan_bsum() {
    __shared__ int sh[256];
    int t = threadIdx.x;
    int v = (t < SCAN_BLOCKS) ? g_bsum[t] : 0;
    sh[t] = v;
    __syncthreads();
    for (int off = 1; off < 256; off <<= 1) {
        int a = (t >= off) ? sh[t - off] : 0;
        __syncthreads();
        sh[t] += a;
        __syncthreads();
    }
    g_boff[t] = sh[t] - v;              // exclusive
    if (t == 255) g_rowptr[N_NODES] = sh[255];
}

__global__ void k_scan_final() {
    int t = threadIdx.x, i = blockIdx.x * 256 + t;
    int lane = t & 31, wid = t >> 5;
    int v = (i < N_NODES) ? g_cnt[i] : 0;
    int x = v;
#pragma unroll
    for (int off = 1; off < 32; off <<= 1) {
        int y = __shfl_up_sync(0xffffffffu, x, off);
        if (lane >= off) x += y;
    }
    __shared__ int ws[8];
    if (lane == 31) ws[wid] = x;
    __syncthreads();
    if (wid == 0 && lane < 8) {
        int y = ws[lane];
#pragma unroll
        for (int off = 1; off < 8; off <<= 1) {
            int z = __shfl_up_sync(0xffu, y, off, 8);
            if (lane >= off) y += z;
        }
        ws[lane] = y;
    }
    __syncthreads();
    int wexcl = (wid > 0) ? ws[wid - 1] : 0;
    if (i < N_NODES) g_rowptr[i] = (x - v) + wexcl + g_boff[blockIdx.x];
}

__global__ void k_scatter(const int* __restrict__ ei) {
    int e = blockIdx.x * blockDim.x + threadIdx.x;
    if (e < N_EDGES) {
        int dst = clampn(ei[N_EDGES + e]);
        int pos = g_rowptr[dst] + atomicAdd(&g_fill[dst], 1);
        g_col[pos] = clampn(ei[e]);
    }
}

// ---------------- GEMM1 on tensor cores: split-TF32 (3xTF32) ----------------
__device__ __forceinline__ void split_tf32(float x, uint32_t& hi, uint32_t& lo) {
    uint32_t h;
    asm("cvt.rna.tf32.f32 %0, %1;" : "=r"(h) : "f"(x));
    float l = x - __uint_as_float(h);
    uint32_t lr;
    asm("cvt.rna.tf32.f32 %0, %1;" : "=r"(lr) : "f"(l));
    hi = h; lo = lr;
}

__device__ __forceinline__ void mma_tf32(float* c, const uint32_t* a, const uint32_t* b) {
    asm volatile(
        "mma.sync.aligned.m16n8k8.row.col.f32.tf32.tf32.f32 "
        "{%0,%1,%2,%3}, {%4,%5,%6,%7}, {%8,%9}, {%0,%1,%2,%3};"
        : "+f"(c[0]), "+f"(c[1]), "+f"(c[2]), "+f"(c[3])
        : "r"(a[0]), "r"(a[1]), "r"(a[2]), "r"(a[3]), "r"(b[0]), "r"(b[1]));
}

// 128x128 block tile, BK=16, 8 warps (4x2), warp tile 32x64, double-buffered.
__global__ __launch_bounds__(256, 1) void k_gemm1(const float* __restrict__ X,
                                                  const float* __restrict__ W) {
    __shared__ float As[2][128][20];   // [row][k], pad 20 -> conflict-free frags
    __shared__ float Bs[2][16][132];   // [k][n],  pad 132 -> conflict-free frags
    int tid = threadIdx.x;
    int wid = tid >> 5, lane = tid & 31;
    int wm = (wid & 3) * 32, wn = (wid >> 2) * 64;
    int m0 = blockIdx.x * 128, n0 = blockIdx.y * 128;
    int g = lane >> 2, tg = lane & 3;

    int arow = tid >> 1;            // 0..127
    int akoff = (tid & 1) * 8;      // 0 or 8
    int brow = tid >> 4;            // 0..15
    int bcol = (tid & 15) * 8;      // 0..120

    float4 aP0, aP1, bP0, bP1;
    {
        int gm = m0 + arow;
        if (gm < N_NODES) {
            const float4* p = (const float4*)(X + (size_t)gm * F_IN + akoff);
            aP0 = p[0]; aP1 = p[1];
        } else { aP0 = aP1 = make_float4(0.f, 0.f, 0.f, 0.f); }
        const float4* q = (const float4*)(W + (size_t)brow * F_H + n0 + bcol);
        bP0 = q[0]; bP1 = q[1];
    }
    *(float4*)&As[0][arow][akoff]     = aP0;
    *(float4*)&As[0][arow][akoff + 4] = aP1;
    *(float4*)&Bs[0][brow][bcol]      = bP0;
    *(float4*)&Bs[0][brow][bcol + 4]  = bP1;
    __syncthreads();

    float acc[2][8][4];
#pragma unroll
    for (int mi = 0; mi < 2; mi++)
#pragma unroll
        for (int ni = 0; ni < 8; ni++)
#pragma unroll
            for (int r = 0; r < 4; r++) acc[mi][ni][r] = 0.f;

    int buf = 0;
    for (int p = 0; p < F_IN / 16; p++) {
        if (p < F_IN / 16 - 1) {
            int k0 = (p + 1) * 16;
            int gm = m0 + arow;
            if (gm < N_NODES) {
                const float4* pp = (const float4*)(X + (size_t)gm * F_IN + k0 + akoff);
                aP0 = pp[0]; aP1 = pp[1];
            } else { aP0 = aP1 = make_float4(0.f, 0.f, 0.f, 0.f); }
            const float4* q = (const float4*)(W + (size_t)(k0 + brow) * F_H + n0 + bcol);
            bP0 = q[0]; bP1 = q[1];
        }
#pragma unroll
        for (int ks = 0; ks < 2; ks++) {
            int kb = ks * 8;
            uint32_t ah[2][4], al[2][4];
#pragma unroll
            for (int mi = 0; mi < 2; mi++) {
                int r0 = wm + mi * 16 + g;
                float a0 = As[buf][r0][kb + tg];
                float a1 = As[buf][r0 + 8][kb + tg];
                float a2 = As[buf][r0][kb + tg + 4];
                float a3 = As[buf][r0 + 8][kb + tg + 4];
                split_tf32(a0, ah[mi][0], al[mi][0]);
                split_tf32(a1, ah[mi][1], al[mi][1]);
                split_tf32(a2, ah[mi][2], al[mi][2]);
                split_tf32(a3, ah[mi][3], al[mi][3]);
            }
            uint32_t bh[8][2], bl[8][2];
#pragma unroll
            for (int ni = 0; ni < 8; ni++) {
                int nc = wn + ni * 8 + g;
                float b0 = Bs[buf][kb + tg][nc];
                float b1 = Bs[buf][kb + tg + 4][nc];
                split_tf32(b0, bh[ni][0], bl[ni][0]);
                split_tf32(b1, bh[ni][1], bl[ni][1]);
            }
#pragma unroll
            for (int mi = 0; mi < 2; mi++)
#pragma unroll
                for (int ni = 0; ni < 8; ni++) {
                    mma_tf32(acc[mi][ni], ah[mi], bh[ni]);   // hi*hi
                    mma_tf32(acc[mi][ni], ah[mi], bl[ni]);   // hi*lo
                    mma_tf32(acc[mi][ni], al[mi], bh[ni]);   // lo*hi
                }
        }
        if (p < F_IN / 16 - 1) {
            buf ^= 1;
            *(float4*)&As[buf][arow][akoff]     = aP0;
            *(float4*)&As[buf][arow][akoff + 4] = aP1;
            *(float4*)&Bs[buf][brow][bcol]      = bP0;
            *(float4*)&Bs[buf][brow][bcol + 4]  = bP1;
            __syncthreads();
        }
    }

#pragma unroll
    for (int mi = 0; mi < 2; mi++) {
        int r0 = m0 + wm + mi * 16 + g;
        int r1 = r0 + 8;
#pragma unroll
        for (int ni = 0; ni < 8; ni++) {
            int col = n0 + wn + ni * 8 + tg * 2;
            if (r0 < N_NODES)
                *(float2*)(g_h1 + (size_t)r0 * F_H + col) =
                    make_float2(acc[mi][ni][0], acc[mi][ni][1]);
            if (r1 < N_NODES)
                *(float2*)(g_h1 + (size_t)r1 * F_H + col) =
                    make_float2(acc[mi][ni][2], acc[mi][ni][3]);
        }
    }
}

// ---------------- attention coefficient dots, layer 1 (warp per node) ----------
__global__ void k_dots1(const float* __restrict__ as1, const float* __restrict__ ad1) {
    int warp = threadIdx.x >> 5, lane = threadIdx.x & 31;
    int n = blockIdx.x * 8 + warp;
    if (n >= N_NODES) return;
    const float* hp = g_h1 + (size_t)n * F_H;
#pragma unroll
    for (int h = 0; h < HEADS; h++) {
        float v = hp[h * 32 + lane];
        float ps = v * as1[h * 32 + lane];
        float pd = v * ad1[h * 32 + lane];
#pragma unroll
        for (int off = 16; off; off >>= 1) {
            ps += __shfl_xor_sync(0xffffffffu, ps, off);
            pd += __shfl_xor_sync(0xffffffffu, pd, off);
        }
        if (lane == 0) { g_als1[n * HEADS + h] = ps; g_ald1[n * HEADS + h] = pd; }
    }
}

// ---------------- layer 1 softmax-aggregate (warp per dst node) ----------------
__global__ void k_agg1(const float* __restrict__ b1) {
    int warp = threadIdx.x >> 5, lane = threadIdx.x & 31;
    int n = blockIdx.x * 8 + warp;
    if (n >= N_NODES) return;
    int row = g_rowptr[n];
    int deg = g_rowptr[n + 1] - row;
    int cnt = deg + 1;
    int h = lane & 7;
    float ald = g_ald1[n * HEADS + h];

    float mh = -1e30f;
    for (int j = lane >> 3; j < cnt; j += 4) {
        int src = (j < deg) ? g_col[row + j] : n;
        mh = fmaxf(mh, lrelu(g_als1[src * HEADS + h] + ald));
    }
    mh = fmaxf(mh, __shfl_xor_sync(0xffffffffu, mh, 8));
    mh = fmaxf(mh, __shfl_xor_sync(0xffffffffu, mh, 16));

    float sh = 0.f;
    for (int j = lane >> 3; j < cnt; j += 4) {
        int src = (j < deg) ? g_col[row + j] : n;
        sh += __expf(lrelu(g_als1[src * HEADS + h] + ald) - mh);
    }
    sh += __shfl_xor_sync(0xffffffffu, sh, 8);
    sh += __shfl_xor_sync(0xffffffffu, sh, 16);
    float rinv = __fdividef(1.f, sh);

    int hl = lane >> 2;
    float mh2  = __shfl_sync(0xffffffffu, mh,   hl);
    float rv2  = __shfl_sync(0xffffffffu, rinv, hl);
    float ald2 = __shfl_sync(0xffffffffu, ald,  hl);
    int c0 = lane * 8;
    float4 acc0 = make_float4(0.f, 0.f, 0.f, 0.f);
    float4 acc1 = make_float4(0.f, 0.f, 0.f, 0.f);
    for (int j = 0; j < cnt; j++) {
        int src = (j < deg) ? g_col[row + j] : n;
        float w = __expf(lrelu(g_als1[src * HEADS + hl] + ald2) - mh2) * rv2;
        const float4* hp = (const float4*)(g_h1 + (size_t)src * F_H + c0);
        float4 v0 = hp[0], v1 = hp[1];
        acc0.x += w * v0.x; acc0.y += w * v0.y; acc0.z += w * v0.z; acc0.w += w * v0.w;
        acc1.x += w * v1.x; acc1.y += w * v1.y; acc1.z += w * v1.z; acc1.w += w * v1.w;
    }
    float4 bb0 = *(const float4*)(b1 + c0);
    float4 bb1 = *(const float4*)(b1 + c0 + 4);
    float4 o0, o1;
    o0.x = fmaxf(acc0.x + bb0.x, 0.f); o0.y = fmaxf(acc0.y + bb0.y, 0.f);
    o0.z = fmaxf(acc0.z + bb0.z, 0.f); o0.w = fmaxf(acc0.w + bb0.w, 0.f);
    o1.x = fmaxf(acc1.x + bb1.x, 0.f); o1.y = fmaxf(acc1.y + bb1.y, 0.f);
    o1.z = fmaxf(acc1.z + bb1.z, 0.f); o1.w = fmaxf(acc1.w + bb1.w, 0.f);
    *(float4*)(g_h1b + (size_t)n * F_H + c0)     = o0;
    *(float4*)(g_h1b + (size_t)n * F_H + c0 + 4) = o1;
}

// ---------------- layer 2 GEMM (50000x16x256) + attention dots ----------------
__global__ void k_gemm2(const float* __restrict__ W2,
                        const float* __restrict__ as2, const float* __restrict__ ad2) {
    __shared__ float sW[F_OUT * 256];
    int tid = threadIdx.x;
    for (int idx = tid; idx < F_OUT * 256; idx += blockDim.x) {
        int j = idx >> 8, k = idx & 255;
        sW[idx] = W2[k * F_OUT + j];
    }
    __syncthreads();
    int warp = tid >> 5, lane = tid & 31;
    int n = blockIdx.x * 8 + warp;
    if (n >= N_NODES) return;
    const float* hp = g_h1b + (size_t)n * 256;
    float acc[F_OUT];
#pragma unroll
    for (int j = 0; j < F_OUT; j++) acc[j] = 0.f;
    for (int k = lane; k < 256; k += 32) {
        float xv = hp[k];
#pragma unroll
        for (int j = 0; j < F_OUT; j++) acc[j] += xv * sW[j * 256 + k];
    }
#pragma unroll
    for (int j = 0; j < F_OUT; j++)
#pragma unroll
        for (int off = 16; off; off >>= 1)
            acc[j] += __shfl_xor_sync(0xffffffffu, acc[j], off);
    if (lane == 0) {
        float s = 0.f, d = 0.f;
#pragma unroll
        for (int j = 0; j < F_OUT; j++) {
            g_h2[n * F_OUT + j] = acc[j];
            s += acc[j] * as2[j];
            d += acc[j] * ad2[j];
        }
        g_als2[n] = s;
        g_ald2[n] = d;
    }
}

// ---------------- layer 2 softmax-aggregate + log_softmax (warp per node) ------
__global__ void k_agg2(const float* __restrict__ b2, float* __restrict__ out) {
    int warp = threadIdx.x >> 5, lane = threadIdx.x & 31;
    int n = blockIdx.x * 8 + warp;
    if (n >= N_NODES) return;
    int row = g_rowptr[n];
    int deg = g_rowptr[n + 1] - row;
    int cnt = deg + 1;
    float ald = g_ald2[n];

    float mx = -1e30f;
    for (int j = lane; j < cnt; j += 32) {
        int src = (j < deg) ? g_col[row + j] : n;
        mx = fmaxf(mx, lrelu(g_als2[src] + ald));
    }
#pragma unroll
    for (int off = 16; off; off >>= 1) mx = fmaxf(mx, __shfl_xor_sync(0xffffffffu, mx, off));

    float s = 0.f;
    for (int j = lane; j < cnt; j += 32) {
        int src = (j < deg) ? g_col[row + j] : n;
        s += __expf(lrelu(g_als2[src] + ald) - mx);
    }
#pragma unroll
    for (int off = 16; off; off >>= 1) s += __shfl_xor_sync(0xffffffffu, s, off);
    float rinv = __fdividef(1.f, s);

    int c = lane & 15, half = lane >> 4;
    float acc = 0.f;
    for (int j = half; j < cnt; j += 2) {
        int src = (j < deg) ? g_col[row + j] : n;
        float w = __expf(lrelu(g_als2[src] + ald) - mx) * rinv;
        acc += w * g_h2[src * F_OUT + c];
    }
    acc += __shfl_xor_sync(0xffffffffu, acc, 16);

    float v = acc + b2[c];
    float m2 = v;
#pragma unroll
    for (int off = 1; off < 16; off <<= 1) m2 = fmaxf(m2, __shfl_xor_sync(0xffffffffu, m2, off));
    float s2 = __expf(v - m2);
#pragma unroll
    for (int off = 1; off < 16; off <<= 1) s2 += __shfl_xor_sync(0xffffffffu, s2, off);
    float o = v - m2 - __logf(s2);
    if (lane < 16) out[n * F_OUT + c] = o;
}

// ---------------- launch ----------------
extern "C" void kernel_launch(void* const* d_in, const int* in_sizes, int n_in,
                              void* d_out, int out_size) {
    const float* x   = (const float*)d_in[0];
    const int*   ei  = (const int*)d_in[1];
    const float* W1  = (const float*)d_in[2];
    const float* as1 = (const float*)d_in[3];
    const float* ad1 = (const float*)d_in[4];
    const float* b1  = (const float*)d_in[5];
    const float* W2  = (const float*)d_in[6];
    const float* as2 = (const float*)d_in[7];
    const float* ad2 = (const float*)d_in[8];
    const float* b2  = (const float*)d_in[9];
    float* out = (float*)d_out;

    k_zero<<<(N_NODES + 255) / 256, 256>>>();
    k_hist<<<(N_EDGES + 255) / 256, 256>>>(ei);
    k_blocksum<<<SCAN_BLOCKS, 256>>>();
    k_scan_bsum<<<1, 256>>>();
    k_scan_final<<<SCAN_BLOCKS, 256>>>();
    k_scatter<<<(N_EDGES + 255) / 256, 256>>>(ei);

    dim3 g1((N_NODES + 127) / 128, F_H / 128);
    k_gemm1<<<g1, 256>>>(x, W1);
    k_dots1<<<(N_NODES + 7) / 8, 256>>>(as1, ad1);
    k_agg1<<<(N_NODES + 7) / 8, 256>>>(b1);
    k_gemm2<<<(N_NODES + 7) / 8, 256>>>(W2, as2, ad2);
    k_agg2<<<(N_NODES + 7) / 8, 256>>>(b2, out);
}